// round 1
// baseline (speedup 1.0000x reference)
#include <cuda_runtime.h>

#define Bb   2
#define QLn  256
#define KLn  256
#define QDn  1024
#define Hn   512
#define C3n  1536
#define EPSf 1e-5f

typedef unsigned long long ull;

// ---------------- device scratch (static, no allocation) ----------------
__device__ __align__(16) float g_WqT[QDn*Hn];     // [d][h] = Wq[h][d]
__device__ __align__(16) float g_WkT[QDn*Hn];
__device__ __align__(16) float g_AuT[Hn*Hn];      // [j][h] = Wu[h, j]      * lnw[j]
__device__ __align__(16) float g_BuT[Hn*Hn];      // [j][h] = Wu[h, H+j]    * lnw[H+j]
__device__ __align__(16) float g_CuT[Hn*Hn];      // [j][h] = Wu[h, 2H+j]   * lnw[2H+j]
__device__ __align__(16) float g_AvT[Hn*Hn];
__device__ __align__(16) float g_BvT[Hn*Hn];
__device__ __align__(16) float g_CvT[Hn*Hn];
__device__ __align__(16) float g_gu[Hn];          // Wu @ ln_w
__device__ __align__(16) float g_cu[Hn];          // Wu @ ln_b + bu
__device__ __align__(16) float g_gv[Hn];
__device__ __align__(16) float g_cv[Hn];
__device__ __align__(16) float g_qproj[Bb*QLn*Hn];
__device__ __align__(16) float g_kproj[Bb*KLn*Hn];
__device__ __align__(16) float g_ruq[Bb*QLn*Hn];  // A_u q
__device__ __align__(16) float g_rvq[Bb*QLn*Hn];  // A_v q
__device__ __align__(16) float g_ruk[Bb*KLn*Hn];  // B_u k
__device__ __align__(16) float g_rvk[Bb*KLn*Hn];  // B_v k

// ---------------- f32x2 packed-fma helpers ----------------
__device__ __forceinline__ ull fma2(ull a, ull b, ull c) {
    ull d;
    asm("fma.rn.f32x2 %0, %1, %2, %3;" : "=l"(d) : "l"(a), "l"(b), "l"(c));
    return d;
}
__device__ __forceinline__ ull pack2(float x) {
    ull d;
    asm("mov.b64 %0, {%1, %1};" : "=l"(d) : "f"(x));
    return d;
}
__device__ __forceinline__ float2 unpack2(ull v) {
    float2 r;
    asm("mov.b64 {%0, %1}, %2;" : "=f"(r.x), "=f"(r.y) : "l"(v));
    return r;
}

// ---------------- prep kernels ----------------
__global__ void prep_transpose(const float* __restrict__ Wq, const float* __restrict__ Wk) {
    int stride = gridDim.x * blockDim.x;
    for (int i = blockIdx.x * blockDim.x + threadIdx.x; i < QDn * Hn; i += stride) {
        int d = i / Hn, h = i - d * Hn;
        g_WqT[i] = Wq[h * QDn + d];
        g_WkT[i] = Wk[h * QDn + d];
    }
}

__global__ void prep_split(const float* __restrict__ Wu, const float* __restrict__ Wv,
                           const float* __restrict__ lnw) {
    int stride = gridDim.x * blockDim.x;
    for (int i = blockIdx.x * blockDim.x + threadIdx.x; i < Hn * Hn; i += stride) {
        int j = i / Hn, h = i - j * Hn;
        float w0 = lnw[j], w1 = lnw[Hn + j], w2 = lnw[2 * Hn + j];
        const float* wu = Wu + h * C3n;
        const float* wv = Wv + h * C3n;
        g_AuT[i] = wu[j] * w0;          g_AvT[i] = wv[j] * w0;
        g_BuT[i] = wu[Hn + j] * w1;     g_BvT[i] = wv[Hn + j] * w1;
        g_CuT[i] = wu[2 * Hn + j] * w2; g_CvT[i] = wv[2 * Hn + j] * w2;
    }
}

__global__ void prep_vec(const float* __restrict__ Wu, const float* __restrict__ bu,
                         const float* __restrict__ Wv, const float* __restrict__ bv,
                         const float* __restrict__ lnw, const float* __restrict__ lnb) {
    int w = (blockIdx.x * blockDim.x + threadIdx.x) >> 5;
    int lane = threadIdx.x & 31;
    if (w >= Hn) return;
    float gu = 0.f, cu = 0.f, gv = 0.f, cv = 0.f;
    for (int c = lane; c < C3n; c += 32) {
        float wl = lnw[c], bl = lnb[c];
        float a = Wu[w * C3n + c], d = Wv[w * C3n + c];
        gu += a * wl; cu += a * bl; gv += d * wl; cv += d * bl;
    }
    #pragma unroll
    for (int o = 16; o; o >>= 1) {
        gu += __shfl_xor_sync(0xffffffffu, gu, o);
        cu += __shfl_xor_sync(0xffffffffu, cu, o);
        gv += __shfl_xor_sync(0xffffffffu, gv, o);
        cv += __shfl_xor_sync(0xffffffffu, cv, o);
    }
    if (lane == 0) {
        g_gu[w] = gu; g_cu[w] = cu + bu[w];
        g_gv[w] = gv; g_cv[w] = cv + bv[w];
    }
}

// ---------------- generic row-major GEMM: C[M,N] = A[M,K] * B[K,N] ----------------
__global__ __launch_bounds__(256) void gemm_rm(const float* __restrict__ A,
                                               const float* __restrict__ Bm,
                                               float* __restrict__ C,
                                               int M, int N, int Kd) {
    __shared__ __align__(16) float As[16][68];  // As[kk][m]
    __shared__ __align__(16) float Bs[16][68];  // Bs[kk][n]
    const int t  = threadIdx.x;
    const int tx = t & 15, ty = t >> 4;
    const int bm = blockIdx.y * 64, bn = blockIdx.x * 64;
    float acc[4][4] = {};
    for (int kb = 0; kb < Kd; kb += 16) {
        #pragma unroll
        for (int l = 0; l < 4; l++) {
            int e = t + l * 256;
            int m = e >> 4, kk = e & 15;
            As[kk][m] = A[(bm + m) * Kd + kb + kk];
            int n = e & 63, k2 = e >> 6;
            Bs[k2][n] = Bm[(kb + k2) * N + bn + n];
        }
        __syncthreads();
        #pragma unroll
        for (int kk = 0; kk < 16; kk++) {
            float4 a = *(const float4*)&As[kk][ty * 4];
            float4 b = *(const float4*)&Bs[kk][tx * 4];
            float aw[4] = {a.x, a.y, a.z, a.w};
            float bw[4] = {b.x, b.y, b.z, b.w};
            #pragma unroll
            for (int i = 0; i < 4; i++)
                #pragma unroll
                for (int j = 0; j < 4; j++)
                    acc[i][j] += aw[i] * bw[j];
        }
        __syncthreads();
    }
    #pragma unroll
    for (int i = 0; i < 4; i++) {
        float4 o = make_float4(acc[i][0], acc[i][1], acc[i][2], acc[i][3]);
        *(float4*)&C[(bm + ty * 4 + i) * N + bn + tx * 4] = o;
    }
}

// ---------------- main fused kernel ----------------
// grid: (KL/128, B*QL); block: 256 threads (tx = h-dir 16, ty = k-dir 16)
// Block computes out[b, q, k0..k0+127] fully: per-pair LN stats + the
// C_u/C_v (q⊙k) contraction (128k x 128h tile, h looped 4x) + gated epilogue.
__global__ __launch_bounds__(256, 1) void gated_main(const float* __restrict__ Wo,
                                                     const float* __restrict__ bo,
                                                     float* __restrict__ out) {
    __shared__ __align__(16) float qrow[Hn];
    __shared__ __align__(16) float KsT[16][132];  // [j][k] scaled K tile
    __shared__ __align__(16) float BuS[16][132];  // [j][h] C_u^T tile
    __shared__ __align__(16) float BvS[16][132];
    __shared__ float muS[128], rsS[128];
    __shared__ float ruqS[128], rvqS[128], guS[128], cuS[128], gvS[128], cvS[128], woS[128];
    __shared__ float sqv[2];

    const int t    = threadIdx.x;
    const int tx   = t & 15;
    const int ty   = t >> 4;
    const int warp = t >> 5;
    const int lane = t & 31;
    const int bq   = blockIdx.y;          // b*QL + q
    const int b    = bq >> 8;
    const int k0   = blockIdx.x * 128;

    const float* qp     = g_qproj + bq * Hn;
    const float* kpbase = g_kproj + (b * KLn + k0) * Hn;

    qrow[t]       = qp[t];
    qrow[t + 256] = qp[t + 256];
    __syncthreads();

    // Sq, Sq2 (warp 0)
    if (warp == 0) {
        float s1 = 0.f, s2 = 0.f;
        #pragma unroll
        for (int j = lane; j < Hn; j += 32) { float v = qrow[j]; s1 += v; s2 += v * v; }
        #pragma unroll
        for (int o = 16; o; o >>= 1) {
            s1 += __shfl_xor_sync(0xffffffffu, s1, o);
            s2 += __shfl_xor_sync(0xffffffffu, s2, o);
        }
        if (lane == 0) { sqv[0] = s1; sqv[1] = s2; }
    }

    // per-k stats: Sk, Sk2, q.k, sum((q_j k_j)^2) — 8 warps x 16 rows
    for (int r = 0; r < 16; r++) {
        int kk = warp * 16 + r;
        const float* kp = kpbase + kk * Hn;
        float sk = 0.f, sk2 = 0.f, d1 = 0.f, d2 = 0.f;
        for (int j = lane; j < Hn; j += 32) {
            float kv = kp[j];
            float p  = kv * qrow[j];
            sk += kv; sk2 += kv * kv; d1 += p; d2 += p * p;
        }
        #pragma unroll
        for (int o = 16; o; o >>= 1) {
            sk  += __shfl_xor_sync(0xffffffffu, sk,  o);
            sk2 += __shfl_xor_sync(0xffffffffu, sk2, o);
            d1  += __shfl_xor_sync(0xffffffffu, d1,  o);
            d2  += __shfl_xor_sync(0xffffffffu, d2,  o);
        }
        if (lane == 0) { muS[kk] = sk + d1; rsS[kk] = sk2 + d2; }
    }
    __syncthreads();
    if (t < 128) {
        float mu = (sqv[0] + muS[t]) * (1.f / C3n);
        float e2 = (sqv[1] + rsS[t]) * (1.f / C3n);
        muS[t] = mu;
        rsS[t] = rsqrtf(e2 - mu * mu + EPSf);
    }

    float partial[8] = {0.f, 0.f, 0.f, 0.f, 0.f, 0.f, 0.f, 0.f};
    const float bo_v = bo[0];

    ull accu[8][4], accv[8][4];

    for (int ht = 0; ht < 4; ht++) {
        const int h0 = ht * 128;
        __syncthreads();  // previous epilogue reads done before overwriting h-arrays
        if (t < 128) {
            ruqS[t] = g_ruq[bq * Hn + h0 + t];
            rvqS[t] = g_rvq[bq * Hn + h0 + t];
            guS[t]  = g_gu[h0 + t];
            cuS[t]  = g_cu[h0 + t];
            gvS[t]  = g_gv[h0 + t];
            cvS[t]  = g_cv[h0 + t];
            woS[t]  = Wo[h0 + t];
        }
        #pragma unroll
        for (int i = 0; i < 8; i++)
            #pragma unroll
            for (int p = 0; p < 4; p++) { accu[i][p] = 0ull; accv[i][p] = 0ull; }

        for (int jc = 0; jc < 32; jc++) {
            const int j0 = jc * 16;
            // stage: KsT[j][k] = kproj[k][j0+j] * qrow[j0+j]; BuS/BvS = C^T tiles
            #pragma unroll
            for (int pp = 0; pp < 2; pp++) {
                int e  = t + pp * 256;
                int kk = e >> 2;
                int jq = e & 3;
                float4 kv = *(const float4*)(kpbase + kk * Hn + j0 + jq * 4);
                float4 qv = *(const float4*)&qrow[j0 + jq * 4];
                KsT[jq * 4 + 0][kk] = kv.x * qv.x;
                KsT[jq * 4 + 1][kk] = kv.y * qv.y;
                KsT[jq * 4 + 2][kk] = kv.z * qv.z;
                KsT[jq * 4 + 3][kk] = kv.w * qv.w;
                int j  = e >> 5;
                int hq = e & 31;
                *(float4*)&BuS[j][hq * 4] = *(const float4*)&g_CuT[(j0 + j) * Hn + h0 + hq * 4];
                *(float4*)&BvS[j][hq * 4] = *(const float4*)&g_CvT[(j0 + j) * Hn + h0 + hq * 4];
            }
            __syncthreads();
            #pragma unroll
            for (int jj = 0; jj < 16; jj++) {
                float4 a0 = *(const float4*)&KsT[jj][ty * 8];
                float4 a1 = *(const float4*)&KsT[jj][ty * 8 + 4];
                ulonglong2 u0 = *(const ulonglong2*)&BuS[jj][tx * 4];
                ulonglong2 u1 = *(const ulonglong2*)&BuS[jj][64 + tx * 4];
                ulonglong2 v0 = *(const ulonglong2*)&BvS[jj][tx * 4];
                ulonglong2 v1 = *(const ulonglong2*)&BvS[jj][64 + tx * 4];
                float av[8] = {a0.x, a0.y, a0.z, a0.w, a1.x, a1.y, a1.z, a1.w};
                #pragma unroll
                for (int i = 0; i < 8; i++) {
                    ull aa = pack2(av[i]);
                    accu[i][0] = fma2(aa, u0.x, accu[i][0]);
                    accu[i][1] = fma2(aa, u0.y, accu[i][1]);
                    accu[i][2] = fma2(aa, u1.x, accu[i][2]);
                    accu[i][3] = fma2(aa, u1.y, accu[i][3]);
                    accv[i][0] = fma2(aa, v0.x, accv[i][0]);
                    accv[i][1] = fma2(aa, v0.y, accv[i][1]);
                    accv[i][2] = fma2(aa, v1.x, accv[i][2]);
                    accv[i][3] = fma2(aa, v1.y, accv[i][3]);
                }
            }
            __syncthreads();
        }

        // epilogue: LN affine terms + gated gelu + Wo-weighted reduce over h
        #pragma unroll
        for (int i = 0; i < 8; i++) {
            const int kl  = ty * 8 + i;
            const float mu = muS[kl];
            const float rs = rsS[kl];
            const float mrs = mu * rs;
            const int kg = b * KLn + k0 + kl;
            const float4* ruk4 = (const float4*)(g_ruk + kg * Hn + h0);
            const float4* rvk4 = (const float4*)(g_rvk + kg * Hn + h0);
            float4 ruA = ruk4[tx], ruB = ruk4[16 + tx];
            float4 rvA = rvk4[tx], rvB = rvk4[16 + tx];
            float rukv[8] = {ruA.x, ruA.y, ruA.z, ruA.w, ruB.x, ruB.y, ruB.z, ruB.w};
            float rvkv[8] = {rvA.x, rvA.y, rvA.z, rvA.w, rvB.x, rvB.y, rvB.z, rvB.w};
            float tu[8], tv[8];
            float2 f;
            f = unpack2(accu[i][0]); tu[0] = f.x; tu[1] = f.y;
            f = unpack2(accu[i][1]); tu[2] = f.x; tu[3] = f.y;
            f = unpack2(accu[i][2]); tu[4] = f.x; tu[5] = f.y;
            f = unpack2(accu[i][3]); tu[6] = f.x; tu[7] = f.y;
            f = unpack2(accv[i][0]); tv[0] = f.x; tv[1] = f.y;
            f = unpack2(accv[i][1]); tv[2] = f.x; tv[3] = f.y;
            f = unpack2(accv[i][2]); tv[4] = f.x; tv[5] = f.y;
            f = unpack2(accv[i][3]); tv[6] = f.x; tv[7] = f.y;
            #pragma unroll
            for (int e = 0; e < 8; e++) {
                int h = (e < 4) ? (tx * 4 + e) : (64 + tx * 4 + (e - 4));
                float U = rs * (tu[e] + ruqS[h] + rukv[e]) - mrs * guS[h] + cuS[h];
                float V = rs * (tv[e] + rvqS[h] + rvkv[e]) - mrs * gvS[h] + cvS[h];
                float G = 0.5f * V * (1.0f + erff(V * 0.70710678118654752440f));
                partial[i] += woS[h] * (U * G);
            }
        }
    }

    // reduce partials across the 16 tx lanes (contiguous half-warp groups)
    #pragma unroll
    for (int i = 0; i < 8; i++) {
        float v = partial[i];
        #pragma unroll
        for (int o = 8; o; o >>= 1) v += __shfl_xor_sync(0xffffffffu, v, o);
        if (tx == 0) out[bq * KLn + k0 + ty * 8 + i] = v + bo_v;
    }
}

// ---------------- launch ----------------
extern "C" void kernel_launch(void* const* d_in, const int* in_sizes, int n_in,
                              void* d_out, int out_size) {
    const float* Q   = (const float*)d_in[0];
    const float* K   = (const float*)d_in[1];
    const float* Wq  = (const float*)d_in[2];
    const float* Wk  = (const float*)d_in[3];
    const float* lnw = (const float*)d_in[4];
    const float* lnb = (const float*)d_in[5];
    const float* Wu  = (const float*)d_in[6];
    const float* bu  = (const float*)d_in[7];
    const float* Wv  = (const float*)d_in[8];
    const float* bv  = (const float*)d_in[9];
    const float* Wo  = (const float*)d_in[10];
    const float* bo  = (const float*)d_in[11];
    float* out = (float*)d_out;

    void *p_wqt, *p_wkt, *p_aut, *p_avt, *p_but, *p_bvt;
    void *p_qp, *p_kp, *p_ruq, *p_rvq, *p_ruk, *p_rvk;
    cudaGetSymbolAddress(&p_wqt, g_WqT);
    cudaGetSymbolAddress(&p_wkt, g_WkT);
    cudaGetSymbolAddress(&p_aut, g_AuT);
    cudaGetSymbolAddress(&p_avt, g_AvT);
    cudaGetSymbolAddress(&p_but, g_BuT);
    cudaGetSymbolAddress(&p_bvt, g_BvT);
    cudaGetSymbolAddress(&p_qp,  g_qproj);
    cudaGetSymbolAddress(&p_kp,  g_kproj);
    cudaGetSymbolAddress(&p_ruq, g_ruq);
    cudaGetSymbolAddress(&p_rvq, g_rvq);
    cudaGetSymbolAddress(&p_ruk, g_ruk);
    cudaGetSymbolAddress(&p_rvk, g_rvk);

    prep_transpose<<<512, 256>>>(Wq, Wk);
    prep_split<<<512, 256>>>(Wu, Wv, lnw);
    prep_vec<<<64, 256>>>(Wu, bu, Wv, bv, lnw, lnb);

    dim3 g88(8, 8);
    gemm_rm<<<g88, 256>>>(Q, (const float*)p_wqt, (float*)p_qp, Bb * QLn, Hn, QDn);
    gemm_rm<<<g88, 256>>>(K, (const float*)p_wkt, (float*)p_kp, Bb * KLn, Hn, QDn);
    gemm_rm<<<g88, 256>>>((const float*)p_qp, (const float*)p_aut, (float*)p_ruq, Bb * QLn, Hn, Hn);
    gemm_rm<<<g88, 256>>>((const float*)p_qp, (const float*)p_avt, (float*)p_rvq, Bb * QLn, Hn, Hn);
    gemm_rm<<<g88, 256>>>((const float*)p_kp, (const float*)p_but, (float*)p_ruk, Bb * KLn, Hn, Hn);
    gemm_rm<<<g88, 256>>>((const float*)p_kp, (const float*)p_bvt, (float*)p_rvk, Bb * KLn, Hn, Hn);

    gated_main<<<dim3(2, 512), 256>>>(Wo, bo, out);
}